// round 3
// baseline (speedup 1.0000x reference)
#include <cuda_runtime.h>
#include <math.h>

#define BATCH 2
#define SEQ 2048
#define DMODEL 768
#define NHEAD 12
#define DHEAD 64
#define MTOT (BATCH*SEQ)

typedef unsigned int uint;

// Scratch (device globals: allocation-free per harness rules)
__device__ float g_Q[MTOT*DMODEL];
__device__ float g_K[MTOT*DMODEL];
__device__ float g_V[MTOT*DMODEL];
__device__ float g_O[MTOT*DMODEL];

// ---------------------------------------------------------------------------
// tf32 helpers
// ---------------------------------------------------------------------------
__device__ __forceinline__ uint cvt_tf32(float x) {
  uint r; asm("cvt.rna.tf32.f32 %0, %1;" : "=r"(r) : "f"(x)); return r;
}
__device__ __forceinline__ void mma_tf32(float4& d, const uint4& a, const uint2& b) {
  asm volatile(
    "mma.sync.aligned.m16n8k8.row.col.f32.tf32.tf32.f32 "
    "{%0,%1,%2,%3}, {%4,%5,%6,%7}, {%8,%9}, {%0,%1,%2,%3};"
    : "+f"(d.x), "+f"(d.y), "+f"(d.z), "+f"(d.w)
    : "r"(a.x), "r"(a.y), "r"(a.z), "r"(a.w), "r"(b.x), "r"(b.y));
}

// ---------------------------------------------------------------------------
// Tensor-core SGEMM (tf32x3, fp32-accurate): C[M,N] = A[M,K] @ W[K,N] + bias
// CTA tile 128x128, BK=16, 256 threads = 8 warps (4x2), warp tile 32x64.
// Operands pre-split into tf32 hi/lo in SMEM, fragment-shuffled layout:
//   sA entry: 12 uints per (mtile,kstep,lane): hi[4] lo[4] pad[4]  (48B stride,
//             conflict-free LDS.128)
//   sB entry:  6 uints per (ntile,kstep,lane): hi[2] lo[2] pad[2]  (24B stride,
//             conflict-free LDS.64)
// Per a*b: 3 MMAs (hi*hi + hi*lo + lo*hi), error ~2^-24.
// ---------------------------------------------------------------------------
#define GBM 128
#define GBN 128
#define GBK 16
#define SA_UINTS (8*2*32*12)   // 6144
#define SB_UINTS (16*2*32*6)   // 6144
#define GEMM_SMEM ((SA_UINTS + SB_UINTS) * 4)  // 49152 B

__global__ __launch_bounds__(256) void sgemm_bias(
    const float* __restrict__ A, const float* __restrict__ W,
    const float* __restrict__ bias, float* __restrict__ C,
    int M, int N, int K) {
  extern __shared__ uint smem[];
  uint* sA = smem;             // [mt(8)][ks(2)][lane(32)][12]
  uint* sB = smem + SA_UINTS;  // [nt(16)][ks(2)][lane(32)][6]

  const int t    = threadIdx.x;
  const int lane = t & 31;
  const int w    = t >> 5;
  const int wm   = w >> 1;     // 0..3  -> warp rows (32 each)
  const int wn   = w & 1;      // 0..1  -> warp cols (64 each)
  const int m0   = blockIdx.y * GBM, n0 = blockIdx.x * GBN;

  // staging assignments
  const int arow = t >> 1;           // 0..127
  const int aks  = t & 1;            // kstep this thread stages
  const int amt  = arow >> 4, ar = arow & 15;
  const int brow = t >> 4;           // 0..15 (k)
  const int bks  = brow >> 3, bkc = brow & 7;
  const int bnc0 = (t & 15) * 4;

  const float* Ap = A + (size_t)(m0 + arow) * K + aks * 8;
  const float* Wp = W + n0 + bnc0;

  float4 ra0 = *(const float4*)(Ap);
  float4 ra1 = *(const float4*)(Ap + 4);
  float4 rb0 = *(const float4*)(Wp + (size_t)brow * N);
  float4 rb1 = *(const float4*)(Wp + (size_t)brow * N + 64);

  float4 acc[2][8];
  #pragma unroll
  for (int i = 0; i < 2; i++)
    #pragma unroll
    for (int j = 0; j < 8; j++) acc[i][j] = make_float4(0.f,0.f,0.f,0.f);

  for (int k0 = 0; k0 < K; k0 += GBK) {
    __syncthreads();   // previous tile's readers done

    { // stage A: this thread owns (amt, aks, row ar), kc = 0..7
      float av[8] = {ra0.x,ra0.y,ra0.z,ra0.w, ra1.x,ra1.y,ra1.z,ra1.w};
      const uint base = ((amt*2 + aks) * 32) * 12;
      #pragma unroll
      for (int kc = 0; kc < 8; kc++) {
        const uint ln  = ((ar & 7) << 2) | (kc & 3);
        const uint reg = ((kc >> 2) << 1) | (ar >> 3);
        const uint hi  = cvt_tf32(av[kc]);
        const float lo = av[kc] - __uint_as_float(hi);
        sA[base + ln*12 + reg]     = hi;
        sA[base + ln*12 + 4 + reg] = cvt_tf32(lo);
      }
    }
    { // stage B: this thread owns k-row brow, cols bnc0+{0..3}, bnc0+64+{0..3}
      float bv[8] = {rb0.x,rb0.y,rb0.z,rb0.w, rb1.x,rb1.y,rb1.z,rb1.w};
      #pragma unroll
      for (int g = 0; g < 2; g++)
        #pragma unroll
        for (int e = 0; e < 4; e++) {
          const int n  = bnc0 + g*64 + e;
          const int nt = n >> 3, nc = n & 7;
          const float v = bv[g*4 + e];
          const uint hi = cvt_tf32(v);
          const float lo = v - __uint_as_float(hi);
          const uint base = ((nt*2 + bks)*32 + ((nc << 2) | (bkc & 3))) * 6;
          const uint reg  = bkc >> 2;
          sB[base + reg]     = hi;
          sB[base + 2 + reg] = cvt_tf32(lo);
        }
    }
    __syncthreads();

    if (k0 + GBK < K) {  // prefetch next tile
      ra0 = *(const float4*)(Ap + k0 + GBK);
      ra1 = *(const float4*)(Ap + k0 + GBK + 4);
      rb0 = *(const float4*)(Wp + (size_t)(k0 + GBK + brow) * N);
      rb1 = *(const float4*)(Wp + (size_t)(k0 + GBK + brow) * N + 64);
    }

    #pragma unroll
    for (int ks = 0; ks < 2; ks++) {
      uint4 ahi[2], alo[2];
      #pragma unroll
      for (int i = 0; i < 2; i++) {
        const uint base = (((wm*2 + i)*2 + ks)*32 + lane) * 12;
        ahi[i] = *(const uint4*)&sA[base];
        alo[i] = *(const uint4*)&sA[base + 4];
      }
      #pragma unroll
      for (int j = 0; j < 8; j++) {
        const uint base = (((wn*8 + j)*2 + ks)*32 + lane) * 6;
        uint2 bhi = *(const uint2*)&sB[base];
        uint2 blo = *(const uint2*)&sB[base + 2];
        #pragma unroll
        for (int i = 0; i < 2; i++) {
          mma_tf32(acc[i][j], ahi[i], bhi);
          mma_tf32(acc[i][j], ahi[i], blo);
          mma_tf32(acc[i][j], alo[i], bhi);
        }
      }
    }
  }

  // epilogue: C frag (m16n8): rows lane/4, lane/4+8; cols (lane%3... (lane&3)*2
  #pragma unroll
  for (int i = 0; i < 2; i++) {
    const int mrow = m0 + (wm*2 + i)*16 + (lane >> 2);
    #pragma unroll
    for (int j = 0; j < 8; j++) {
      const int col = n0 + (wn*8 + j)*8 + (lane & 3)*2;
      const float2 bv = *(const float2*)(bias + col);
      float2 lo = make_float2(acc[i][j].x + bv.x, acc[i][j].y + bv.y);
      float2 hi = make_float2(acc[i][j].z + bv.x, acc[i][j].w + bv.y);
      *(float2*)(C + (size_t)mrow * N + col)       = lo;
      *(float2*)(C + (size_t)(mrow + 8) * N + col) = hi;
    }
  }
}

// ---------------------------------------------------------------------------
// Flash attention (causal, unscaled -- faithful). Round-1 version (best
// issue rate). One thread per query row, BR=128, BC=32.
// ---------------------------------------------------------------------------
#define BR 128
#define BC 32

__global__ __launch_bounds__(128) void flash_attn(
    const float* __restrict__ Q, const float* __restrict__ K,
    const float* __restrict__ V, float* __restrict__ O) {
  const int b    = blockIdx.z;
  const int h    = blockIdx.y;
  const int q0   = (gridDim.x - 1 - blockIdx.x) * BR;  // heavy blocks first
  const int tid  = threadIdx.x;
  const int qidx = q0 + tid;

  __shared__ float Ks[BC][DHEAD];
  __shared__ float Vs[BC][DHEAD];

  float q[DHEAD], o[DHEAD];
  const float* qp = Q + ((size_t)(b*SEQ + qidx))*DMODEL + h*DHEAD;
  #pragma unroll
  for (int d = 0; d < DHEAD; d += 4) {
    float4 v4 = *(const float4*)(qp + d);
    q[d]=v4.x; q[d+1]=v4.y; q[d+2]=v4.z; q[d+3]=v4.w;
    o[d]=0.f;  o[d+1]=0.f;  o[d+2]=0.f;  o[d+3]=0.f;
  }
  float m = -INFINITY, l = 0.f;

  const int ktiles = (q0 + BR) / BC;
  for (int kt = 0; kt < ktiles; kt++) {
    const int j0 = kt * BC;

    #pragma unroll
    for (int i = tid*4; i < BC*DHEAD; i += 128*4) {
      const int j = i >> 6, d = i & 63;
      const size_t base = ((size_t)(b*SEQ + j0 + j))*DMODEL + h*DHEAD + d;
      *(float4*)&Ks[j][d] = *(const float4*)(K + base);
      *(float4*)&Vs[j][d] = *(const float4*)(V + base);
    }
    __syncthreads();

    float s[BC];
    #pragma unroll
    for (int j = 0; j < BC; j++) s[j] = 0.f;
    #pragma unroll 4
    for (int d = 0; d < DHEAD; d += 4) {
      const float qa=q[d], qb=q[d+1], qc=q[d+2], qd=q[d+3];
      #pragma unroll
      for (int j = 0; j < BC; j++) {
        float4 k4 = *(const float4*)&Ks[j][d];
        s[j] += qa*k4.x + qb*k4.y + qc*k4.z + qd*k4.w;
      }
    }

    float mnew = m;
    #pragma unroll
    for (int j = 0; j < BC; j++) {
      s[j] = (j0 + j <= qidx) ? s[j] : -INFINITY;
      mnew = fmaxf(mnew, s[j]);
    }
    const float scale = __expf(m - mnew);
    l *= scale;
    #pragma unroll
    for (int d = 0; d < DHEAD; d++) o[d] *= scale;

    #pragma unroll 4
    for (int j = 0; j < BC; j++) {
      const float p = __expf(s[j] - mnew);
      l += p;
      #pragma unroll
      for (int d = 0; d < DHEAD; d += 4) {
        float4 v4 = *(const float4*)&Vs[j][d];
        o[d]+=p*v4.x; o[d+1]+=p*v4.y; o[d+2]+=p*v4.z; o[d+3]+=p*v4.w;
      }
    }
    m = mnew;
    __syncthreads();
  }

  const float inv = 1.0f / l;
  float* op = O + ((size_t)(b*SEQ + qidx))*DMODEL + h*DHEAD;
  #pragma unroll
  for (int d = 0; d < DHEAD; d += 4) {
    float4 v4 = make_float4(o[d]*inv, o[d+1]*inv, o[d+2]*inv, o[d+3]*inv);
    *(float4*)(op + d) = v4;
  }
}

// ---------------------------------------------------------------------------
// Launch
// ---------------------------------------------------------------------------
extern "C" void kernel_launch(void* const* d_in, const int* in_sizes, int n_in,
                              void* d_out, int out_size) {
  const float* query = (const float*)d_in[0];
  const float* key_  = (const float*)d_in[1];
  const float* value = (const float*)d_in[2];
  // d_in[3] = mask (causal tril) -- handled analytically
  const float* W_q = (const float*)d_in[4];
  const float* b_q = (const float*)d_in[5];
  const float* W_k = (const float*)d_in[6];
  const float* b_k = (const float*)d_in[7];
  const float* W_v = (const float*)d_in[8];
  const float* b_v = (const float*)d_in[9];
  const float* W_o = (const float*)d_in[10];
  const float* b_o = (const float*)d_in[11];
  float* out = (float*)d_out;

  float *Qb, *Kb, *Vb, *Ob;
  cudaGetSymbolAddress((void**)&Qb, g_Q);
  cudaGetSymbolAddress((void**)&Kb, g_K);
  cudaGetSymbolAddress((void**)&Vb, g_V);
  cudaGetSymbolAddress((void**)&Ob, g_O);

  static int smem_set = 0;
  if (!smem_set) {
    cudaFuncSetAttribute(sgemm_bias,
        cudaFuncAttributeMaxDynamicSharedMemorySize, GEMM_SMEM);
    smem_set = 1;
  }

  dim3 gemm_grid(DMODEL / GBN, MTOT / GBM);   // 6 x 32 = 192 CTAs
  sgemm_bias<<<gemm_grid, 256, GEMM_SMEM>>>(query, W_q, b_q, Qb, MTOT, DMODEL, DMODEL);
  sgemm_bias<<<gemm_grid, 256, GEMM_SMEM>>>(key_,  W_k, b_k, Kb, MTOT, DMODEL, DMODEL);
  sgemm_bias<<<gemm_grid, 256, GEMM_SMEM>>>(value, W_v, b_v, Vb, MTOT, DMODEL, DMODEL);

  flash_attn<<<dim3(SEQ / BR, NHEAD, BATCH), BR>>>(Qb, Kb, Vb, Ob);

  sgemm_bias<<<gemm_grid, 256, GEMM_SMEM>>>(Ob, W_o, b_o, out, MTOT, DMODEL, DMODEL);
}

// round 4
// speedup vs baseline: 1.5480x; 1.5480x over previous
#include <cuda_runtime.h>
#include <cuda_bf16.h>
#include <math.h>

#define BATCH 2
#define SEQ 2048
#define DMODEL 768
#define NHEAD 12
#define DHEAD 64
#define MTOT (BATCH*SEQ)
#define K2 (3*DMODEL)   // 2304: [hi|hi|lo] x [hi|lo|hi] concatenated contraction

typedef unsigned int uint;

// Scratch (device globals: allocation-free per harness rules)
__device__ float g_Q[MTOT*DMODEL];
__device__ float g_K[MTOT*DMODEL];
__device__ float g_V[MTOT*DMODEL];
__device__ float g_O[MTOT*DMODEL];
__device__ __nv_bfloat16 g_Asp[(size_t)MTOT*K2];    // split activations [M][2304]
__device__ __nv_bfloat16 g_Wsp[(size_t)K2*DMODEL];  // split weights     [2304][768]

// ---------------------------------------------------------------------------
// MMA / ldmatrix helpers
// ---------------------------------------------------------------------------
__device__ __forceinline__ void ldsm_x4(uint4& r, uint addr) {
  asm volatile("ldmatrix.sync.aligned.m8n8.x4.shared.b16 {%0,%1,%2,%3}, [%4];"
    : "=r"(r.x),"=r"(r.y),"=r"(r.z),"=r"(r.w) : "r"(addr));
}
__device__ __forceinline__ void ldsm_x4t(uint4& r, uint addr) {
  asm volatile("ldmatrix.sync.aligned.m8n8.x4.trans.shared.b16 {%0,%1,%2,%3}, [%4];"
    : "=r"(r.x),"=r"(r.y),"=r"(r.z),"=r"(r.w) : "r"(addr));
}
__device__ __forceinline__ void mma_bf16(float4& d, const uint4& a, uint b0, uint b1) {
  asm volatile("mma.sync.aligned.m16n8k16.row.col.f32.bf16.bf16.f32 "
    "{%0,%1,%2,%3}, {%4,%5,%6,%7}, {%8,%9}, {%0,%1,%2,%3};"
    : "+f"(d.x),"+f"(d.y),"+f"(d.z),"+f"(d.w)
    : "r"(a.x),"r"(a.y),"r"(a.z),"r"(a.w), "r"(b0),"r"(b1));
}

// ---------------------------------------------------------------------------
// Pre-pass: split fp32 into bf16 hi/lo, concatenated along K.
// Activations X[M][768] -> Y[M][2304] = [hi | hi | lo]
// ---------------------------------------------------------------------------
__global__ void split_act(const float* __restrict__ X,
                          __nv_bfloat16* __restrict__ Y, int M) {
  const int i = (blockIdx.x*256 + threadIdx.x)*4;
  if (i >= M*DMODEL) return;
  float4 v = *(const float4*)(X + i);
  const int m = i / DMODEL, k = i - m*DMODEL;
  float vv[4] = {v.x, v.y, v.z, v.w};
  __nv_bfloat16 h[4], l[4];
  #pragma unroll
  for (int e = 0; e < 4; e++) {
    h[e] = __float2bfloat16_rn(vv[e]);
    l[e] = __float2bfloat16_rn(vv[e] - __bfloat162float(h[e]));
  }
  __nv_bfloat16* row = Y + (size_t)m*K2;
  *(uint2*)(row + k)            = *(uint2*)h;
  *(uint2*)(row + DMODEL + k)   = *(uint2*)h;
  *(uint2*)(row + 2*DMODEL + k) = *(uint2*)l;
}

// Weights W[768][768] -> W2[2304][768]: rows [hi | lo | hi]
__global__ void split_w(const float* __restrict__ W,
                        __nv_bfloat16* __restrict__ W2) {
  const int i = (blockIdx.x*256 + threadIdx.x)*4;
  if (i >= DMODEL*DMODEL) return;
  float4 v = *(const float4*)(W + i);
  const int k = i / DMODEL, n = i - k*DMODEL;
  float vv[4] = {v.x, v.y, v.z, v.w};
  __nv_bfloat16 h[4], l[4];
  #pragma unroll
  for (int e = 0; e < 4; e++) {
    h[e] = __float2bfloat16_rn(vv[e]);
    l[e] = __float2bfloat16_rn(vv[e] - __bfloat162float(h[e]));
  }
  *(uint2*)(W2 + (size_t)k*DMODEL + n)              = *(uint2*)h;
  *(uint2*)(W2 + (size_t)(DMODEL + k)*DMODEL + n)   = *(uint2*)l;
  *(uint2*)(W2 + (size_t)(2*DMODEL + k)*DMODEL + n) = *(uint2*)h;
}

// ---------------------------------------------------------------------------
// bf16 tensor-core GEMM: C[4096,768] = A2[4096,2304] @ W2[2304,768] + bias
// CTA 128x128, BK=32, 256 thr = 8 warps (2m x 4n), warp tile 64x32.
// Double-buffered SMEM; ldmatrix.x4 (A, 80B-padded rows) + x4.trans (B, XOR
// swizzle); 32 HMMA per warp per k32 iter.
// ---------------------------------------------------------------------------
#define SM_A_BUF 10240            // 128 rows * 80B
#define SM_B_BUF 8192             // 32 rows * 256B
#define AOFF(m,c) ((m)*80 + (c)*16)
#define BOFF(k,c) ((k)*256 + (((c) ^ ((k)&7))*16))

__global__ __launch_bounds__(256) void gemm_bf16x3(
    const __nv_bfloat16* __restrict__ A2, const __nv_bfloat16* __restrict__ B2,
    const float* __restrict__ bias, float* __restrict__ C) {
  __shared__ __align__(16) unsigned char smraw[2*SM_A_BUF + 2*SM_B_BUF];
  const int t = threadIdx.x, lane = t & 31, w = t >> 5;
  const int wm = w >> 2, wn = w & 3;
  const int m0 = blockIdx.y * 128, n0 = blockIdx.x * 128;
  const uint sb = (uint)__cvta_generic_to_shared(smraw);
  const uint sA[2] = {sb, sb + SM_A_BUF};
  const uint sB[2] = {sb + 2*SM_A_BUF, sb + 2*SM_A_BUF + SM_B_BUF};

  // staging assignments (each thread: 2 chunks of A, 2 of B)
  const int ar = t >> 2, ac = t & 3;    // A rows ar, ar+64; 16B chunk ac
  const int br = t >> 4, bc = t & 15;   // B rows br, br+16; chunk bc
  const __nv_bfloat16* gA = A2 + (size_t)(m0 + ar)*K2 + ac*8;
  const __nv_bfloat16* gB = B2 + (size_t)br*DMODEL + n0 + bc*8;

  uint4 ra0 = *(const uint4*)(gA);
  uint4 ra1 = *(const uint4*)(gA + (size_t)64*K2);
  uint4 rb0 = *(const uint4*)(gB);
  uint4 rb1 = *(const uint4*)(gB + (size_t)16*DMODEL);

  // STS buf 0
  *(uint4*)(smraw + AOFF(ar,ac))                 = ra0;
  *(uint4*)(smraw + AOFF(ar+64,ac))              = ra1;
  *(uint4*)(smraw + 2*SM_A_BUF + BOFF(br,bc))    = rb0;
  *(uint4*)(smraw + 2*SM_A_BUF + BOFF(br+16,bc)) = rb1;

  float4 acc[4][4];
  #pragma unroll
  for (int i = 0; i < 4; i++)
    #pragma unroll
    for (int j = 0; j < 4; j++) acc[i][j] = make_float4(0.f,0.f,0.f,0.f);

  const int ITERS = K2 / 32;   // 72
  for (int it = 0; it < ITERS; it++) {
    __syncthreads();
    const bool pre = (it + 1) < ITERS;
    if (pre) {
      const int k0 = (it + 1) * 32;
      ra0 = *(const uint4*)(gA + k0);
      ra1 = *(const uint4*)(gA + (size_t)64*K2 + k0);
      rb0 = *(const uint4*)(gB + (size_t)k0*DMODEL);
      rb1 = *(const uint4*)(gB + (size_t)(k0+16)*DMODEL);
    }
    const uint cA = sA[it & 1], cB = sB[it & 1];

    #pragma unroll
    for (int ks = 0; ks < 2; ks++) {
      uint4 fa[4];
      #pragma unroll
      for (int i = 0; i < 4; i++)
        ldsm_x4(fa[i], cA + AOFF(wm*64 + i*16 + (lane & 15), ks*2 + (lane >> 4)));
      uint4 fb[2];
      #pragma unroll
      for (int j2 = 0; j2 < 2; j2++)
        ldsm_x4t(fb[j2], cB + BOFF(ks*16 + (lane & 15),
                                   wn*4 + j2*2 + (lane >> 4)));
      #pragma unroll
      for (int i = 0; i < 4; i++) {
        mma_bf16(acc[i][0], fa[i], fb[0].x, fb[0].y);
        mma_bf16(acc[i][1], fa[i], fb[0].z, fb[0].w);
        mma_bf16(acc[i][2], fa[i], fb[1].x, fb[1].y);
        mma_bf16(acc[i][3], fa[i], fb[1].z, fb[1].w);
      }
    }

    if (pre) {
      unsigned char* d = smraw + ((it & 1) ? 0 : SM_A_BUF);
      *(uint4*)(d + AOFF(ar,ac))    = ra0;
      *(uint4*)(d + AOFF(ar+64,ac)) = ra1;
      unsigned char* e = smraw + 2*SM_A_BUF + ((it & 1) ? 0 : SM_B_BUF);
      *(uint4*)(e + BOFF(br,bc))    = rb0;
      *(uint4*)(e + BOFF(br+16,bc)) = rb1;
    }
  }

  #pragma unroll
  for (int i = 0; i < 4; i++) {
    const int r0 = m0 + wm*64 + i*16 + (lane >> 2);
    #pragma unroll
    for (int j = 0; j < 4; j++) {
      const int cN = n0 + wn*32 + j*8 + (lane & 3)*2;
      const float2 bv = *(const float2*)(bias + cN);
      *(float2*)(C + (size_t)r0*DMODEL + cN) =
          make_float2(acc[i][j].x + bv.x, acc[i][j].y + bv.y);
      *(float2*)(C + (size_t)(r0+8)*DMODEL + cN) =
          make_float2(acc[i][j].z + bv.x, acc[i][j].w + bv.y);
    }
  }
}

// ---------------------------------------------------------------------------
// Flash attention (causal, unscaled -- faithful). R1 version.
// One thread per query row, BR=128 rows/CTA, BC=32 key tiles.
// ---------------------------------------------------------------------------
#define BR 128
#define BC 32

__global__ __launch_bounds__(128) void flash_attn(
    const float* __restrict__ Q, const float* __restrict__ K,
    const float* __restrict__ V, float* __restrict__ O) {
  const int b    = blockIdx.z;
  const int h    = blockIdx.y;
  const int q0   = (gridDim.x - 1 - blockIdx.x) * BR;  // heavy blocks first
  const int tid  = threadIdx.x;
  const int qidx = q0 + tid;

  __shared__ float Ks[BC][DHEAD];
  __shared__ float Vs[BC][DHEAD];

  float q[DHEAD], o[DHEAD];
  const float* qp = Q + ((size_t)(b*SEQ + qidx))*DMODEL + h*DHEAD;
  #pragma unroll
  for (int d = 0; d < DHEAD; d += 4) {
    float4 v4 = *(const float4*)(qp + d);
    q[d]=v4.x; q[d+1]=v4.y; q[d+2]=v4.z; q[d+3]=v4.w;
    o[d]=0.f;  o[d+1]=0.f;  o[d+2]=0.f;  o[d+3]=0.f;
  }
  float m = -INFINITY, l = 0.f;

  const int ktiles = (q0 + BR) / BC;
  for (int kt = 0; kt < ktiles; kt++) {
    const int j0 = kt * BC;

    #pragma unroll
    for (int i = tid*4; i < BC*DHEAD; i += 128*4) {
      const int j = i >> 6, d = i & 63;
      const size_t base = ((size_t)(b*SEQ + j0 + j))*DMODEL + h*DHEAD + d;
      *(float4*)&Ks[j][d] = *(const float4*)(K + base);
      *(float4*)&Vs[j][d] = *(const float4*)(V + base);
    }
    __syncthreads();

    float s[BC];
    #pragma unroll
    for (int j = 0; j < BC; j++) s[j] = 0.f;
    #pragma unroll 4
    for (int d = 0; d < DHEAD; d += 4) {
      const float qa=q[d], qb=q[d+1], qc=q[d+2], qd=q[d+3];
      #pragma unroll
      for (int j = 0; j < BC; j++) {
        float4 k4 = *(const float4*)&Ks[j][d];
        s[j] += qa*k4.x + qb*k4.y + qc*k4.z + qd*k4.w;
      }
    }

    float mnew = m;
    #pragma unroll
    for (int j = 0; j < BC; j++) {
      s[j] = (j0 + j <= qidx) ? s[j] : -INFINITY;
      mnew = fmaxf(mnew, s[j]);
    }
    const float scale = __expf(m - mnew);
    l *= scale;
    #pragma unroll
    for (int d = 0; d < DHEAD; d++) o[d] *= scale;

    #pragma unroll 4
    for (int j = 0; j < BC; j++) {
      const float p = __expf(s[j] - mnew);
      l += p;
      #pragma unroll
      for (int d = 0; d < DHEAD; d += 4) {
        float4 v4 = *(const float4*)&Vs[j][d];
        o[d]+=p*v4.x; o[d+1]+=p*v4.y; o[d+2]+=p*v4.z; o[d+3]+=p*v4.w;
      }
    }
    m = mnew;
    __syncthreads();
  }

  const float inv = 1.0f / l;
  float* op = O + ((size_t)(b*SEQ + qidx))*DMODEL + h*DHEAD;
  #pragma unroll
  for (int d = 0; d < DHEAD; d += 4) {
    float4 v4 = make_float4(o[d]*inv, o[d+1]*inv, o[d+2]*inv, o[d+3]*inv);
    *(float4*)(op + d) = v4;
  }
}

// ---------------------------------------------------------------------------
// Launch: (split + GEMM) x3 -> flash -> (split + GEMM)
// ---------------------------------------------------------------------------
extern "C" void kernel_launch(void* const* d_in, const int* in_sizes, int n_in,
                              void* d_out, int out_size) {
  const float* query = (const float*)d_in[0];
  const float* key_  = (const float*)d_in[1];
  const float* value = (const float*)d_in[2];
  // d_in[3] = mask (causal tril) -- handled analytically
  const float* W_q = (const float*)d_in[4];
  const float* b_q = (const float*)d_in[5];
  const float* W_k = (const float*)d_in[6];
  const float* b_k = (const float*)d_in[7];
  const float* W_v = (const float*)d_in[8];
  const float* b_v = (const float*)d_in[9];
  const float* W_o = (const float*)d_in[10];
  const float* b_o = (const float*)d_in[11];
  float* out = (float*)d_out;

  float *Qb, *Kb, *Vb, *Ob;
  __nv_bfloat16 *Asp, *Wsp;
  cudaGetSymbolAddress((void**)&Qb, g_Q);
  cudaGetSymbolAddress((void**)&Kb, g_K);
  cudaGetSymbolAddress((void**)&Vb, g_V);
  cudaGetSymbolAddress((void**)&Ob, g_O);
  cudaGetSymbolAddress((void**)&Asp, g_Asp);
  cudaGetSymbolAddress((void**)&Wsp, g_Wsp);

  const int act_blocks = (MTOT*DMODEL/4 + 255)/256;     // 3072
  const int w_blocks   = (DMODEL*DMODEL/4 + 255)/256;   // 576
  dim3 gg(DMODEL/128, MTOT/128);                        // 6 x 32

  split_act<<<act_blocks, 256>>>(query, Asp, MTOT);
  split_w<<<w_blocks, 256>>>(W_q, Wsp);
  gemm_bf16x3<<<gg, 256>>>(Asp, Wsp, b_q, Qb);

  split_act<<<act_blocks, 256>>>(key_, Asp, MTOT);
  split_w<<<w_blocks, 256>>>(W_k, Wsp);
  gemm_bf16x3<<<gg, 256>>>(Asp, Wsp, b_k, Kb);

  split_act<<<act_blocks, 256>>>(value, Asp, MTOT);
  split_w<<<w_blocks, 256>>>(W_v, Wsp);
  gemm_bf16x3<<<gg, 256>>>(Asp, Wsp, b_v, Vb);

  flash_attn<<<dim3(SEQ/BR, NHEAD, BATCH), BR>>>(Qb, Kb, Vb, Ob);

  split_act<<<act_blocks, 256>>>(Ob, Asp, MTOT);
  split_w<<<w_blocks, 256>>>(W_o, Wsp);
  gemm_bf16x3<<<gg, 256>>>(Asp, Wsp, b_o, out);
}

// round 5
// speedup vs baseline: 4.0695x; 2.6288x over previous
#include <cuda_runtime.h>
#include <cuda_bf16.h>
#include <math.h>

#define BATCH 2
#define SEQ 2048
#define DMODEL 768
#define NHEAD 12
#define DHEAD 64
#define MTOT (BATCH*SEQ)
#define K2 (3*DMODEL)   // 2304: [hi|hi|lo] x [hi|lo|hi] concatenated contraction

typedef unsigned int uint;

// Scratch (device globals: allocation-free per harness rules)
__device__ float g_Q[MTOT*DMODEL];
__device__ float g_K[MTOT*DMODEL];
__device__ float g_V[MTOT*DMODEL];
__device__ float g_O[MTOT*DMODEL];
__device__ __nv_bfloat16 g_Asp[(size_t)MTOT*K2];    // split activations [M][2304]
__device__ __nv_bfloat16 g_Wsp[(size_t)K2*DMODEL];  // split weights     [2304][768]

// ---------------------------------------------------------------------------
// MMA / ldmatrix helpers
// ---------------------------------------------------------------------------
__device__ __forceinline__ void ldsm_x4(uint4& r, uint addr) {
  asm volatile("ldmatrix.sync.aligned.m8n8.x4.shared.b16 {%0,%1,%2,%3}, [%4];"
    : "=r"(r.x),"=r"(r.y),"=r"(r.z),"=r"(r.w) : "r"(addr));
}
__device__ __forceinline__ void ldsm_x4t(uint4& r, uint addr) {
  asm volatile("ldmatrix.sync.aligned.m8n8.x4.trans.shared.b16 {%0,%1,%2,%3}, [%4];"
    : "=r"(r.x),"=r"(r.y),"=r"(r.z),"=r"(r.w) : "r"(addr));
}
__device__ __forceinline__ void mma_bf16(float4& d, const uint4& a, uint b0, uint b1) {
  asm volatile("mma.sync.aligned.m16n8k16.row.col.f32.bf16.bf16.f32 "
    "{%0,%1,%2,%3}, {%4,%5,%6,%7}, {%8,%9}, {%0,%1,%2,%3};"
    : "+f"(d.x),"+f"(d.y),"+f"(d.z),"+f"(d.w)
    : "r"(a.x),"r"(a.y),"r"(a.z),"r"(a.w), "r"(b0),"r"(b1));
}
__device__ __forceinline__ uint packbf(__nv_bfloat16 a, __nv_bfloat16 b) {
  __nv_bfloat162 p = __halves2bfloat162(a, b);
  return *(uint*)&p;
}

// ---------------------------------------------------------------------------
// Pre-pass: split fp32 into bf16 hi/lo, concatenated along K.
// ---------------------------------------------------------------------------
__global__ void split_act(const float* __restrict__ X,
                          __nv_bfloat16* __restrict__ Y, int M) {
  const int i = (blockIdx.x*256 + threadIdx.x)*4;
  if (i >= M*DMODEL) return;
  float4 v = *(const float4*)(X + i);
  const int m = i / DMODEL, k = i - m*DMODEL;
  float vv[4] = {v.x, v.y, v.z, v.w};
  __nv_bfloat16 h[4], l[4];
  #pragma unroll
  for (int e = 0; e < 4; e++) {
    h[e] = __float2bfloat16_rn(vv[e]);
    l[e] = __float2bfloat16_rn(vv[e] - __bfloat162float(h[e]));
  }
  __nv_bfloat16* row = Y + (size_t)m*K2;
  *(uint2*)(row + k)            = *(uint2*)h;
  *(uint2*)(row + DMODEL + k)   = *(uint2*)h;
  *(uint2*)(row + 2*DMODEL + k) = *(uint2*)l;
}

__global__ void split_w(const float* __restrict__ W,
                        __nv_bfloat16* __restrict__ W2) {
  const int i = (blockIdx.x*256 + threadIdx.x)*4;
  if (i >= DMODEL*DMODEL) return;
  float4 v = *(const float4*)(W + i);
  const int k = i / DMODEL, n = i - k*DMODEL;
  float vv[4] = {v.x, v.y, v.z, v.w};
  __nv_bfloat16 h[4], l[4];
  #pragma unroll
  for (int e = 0; e < 4; e++) {
    h[e] = __float2bfloat16_rn(vv[e]);
    l[e] = __float2bfloat16_rn(vv[e] - __bfloat162float(h[e]));
  }
  *(uint2*)(W2 + (size_t)k*DMODEL + n)              = *(uint2*)h;
  *(uint2*)(W2 + (size_t)(DMODEL + k)*DMODEL + n)   = *(uint2*)l;
  *(uint2*)(W2 + (size_t)(2*DMODEL + k)*DMODEL + n) = *(uint2*)h;
}

// ---------------------------------------------------------------------------
// bf16 tensor-core GEMM (unchanged from R4 -- verified working)
// ---------------------------------------------------------------------------
#define SM_A_BUF 10240
#define SM_B_BUF 8192
#define AOFF(m,c) ((m)*80 + (c)*16)
#define BOFF(k,c) ((k)*256 + (((c) ^ ((k)&7))*16))

__global__ __launch_bounds__(256) void gemm_bf16x3(
    const __nv_bfloat16* __restrict__ A2, const __nv_bfloat16* __restrict__ B2,
    const float* __restrict__ bias, float* __restrict__ C) {
  __shared__ __align__(16) unsigned char smraw[2*SM_A_BUF + 2*SM_B_BUF];
  const int t = threadIdx.x, lane = t & 31, w = t >> 5;
  const int wm = w >> 2, wn = w & 3;
  const int m0 = blockIdx.y * 128, n0 = blockIdx.x * 128;
  const uint sb = (uint)__cvta_generic_to_shared(smraw);
  const uint sA[2] = {sb, sb + SM_A_BUF};
  const uint sB[2] = {sb + 2*SM_A_BUF, sb + 2*SM_A_BUF + SM_B_BUF};

  const int ar = t >> 2, ac = t & 3;
  const int br = t >> 4, bc = t & 15;
  const __nv_bfloat16* gA = A2 + (size_t)(m0 + ar)*K2 + ac*8;
  const __nv_bfloat16* gB = B2 + (size_t)br*DMODEL + n0 + bc*8;

  uint4 ra0 = *(const uint4*)(gA);
  uint4 ra1 = *(const uint4*)(gA + (size_t)64*K2);
  uint4 rb0 = *(const uint4*)(gB);
  uint4 rb1 = *(const uint4*)(gB + (size_t)16*DMODEL);

  *(uint4*)(smraw + AOFF(ar,ac))                 = ra0;
  *(uint4*)(smraw + AOFF(ar+64,ac))              = ra1;
  *(uint4*)(smraw + 2*SM_A_BUF + BOFF(br,bc))    = rb0;
  *(uint4*)(smraw + 2*SM_A_BUF + BOFF(br+16,bc)) = rb1;

  float4 acc[4][4];
  #pragma unroll
  for (int i = 0; i < 4; i++)
    #pragma unroll
    for (int j = 0; j < 4; j++) acc[i][j] = make_float4(0.f,0.f,0.f,0.f);

  const int ITERS = K2 / 32;
  for (int it = 0; it < ITERS; it++) {
    __syncthreads();
    const bool pre = (it + 1) < ITERS;
    if (pre) {
      const int k0 = (it + 1) * 32;
      ra0 = *(const uint4*)(gA + k0);
      ra1 = *(const uint4*)(gA + (size_t)64*K2 + k0);
      rb0 = *(const uint4*)(gB + (size_t)k0*DMODEL);
      rb1 = *(const uint4*)(gB + (size_t)(k0+16)*DMODEL);
    }
    const uint cA = sA[it & 1], cB = sB[it & 1];

    #pragma unroll
    for (int ks = 0; ks < 2; ks++) {
      uint4 fa[4];
      #pragma unroll
      for (int i = 0; i < 4; i++)
        ldsm_x4(fa[i], cA + AOFF(wm*64 + i*16 + (lane & 15), ks*2 + (lane >> 4)));
      uint4 fb[2];
      #pragma unroll
      for (int j2 = 0; j2 < 2; j2++)
        ldsm_x4t(fb[j2], cB + BOFF(ks*16 + (lane & 15),
                                   wn*4 + j2*2 + (lane >> 4)));
      #pragma unroll
      for (int i = 0; i < 4; i++) {
        mma_bf16(acc[i][0], fa[i], fb[0].x, fb[0].y);
        mma_bf16(acc[i][1], fa[i], fb[0].z, fb[0].w);
        mma_bf16(acc[i][2], fa[i], fb[1].x, fb[1].y);
        mma_bf16(acc[i][3], fa[i], fb[1].z, fb[1].w);
      }
    }

    if (pre) {
      unsigned char* d = smraw + ((it & 1) ? 0 : SM_A_BUF);
      *(uint4*)(d + AOFF(ar,ac))    = ra0;
      *(uint4*)(d + AOFF(ar+64,ac)) = ra1;
      unsigned char* e = smraw + 2*SM_A_BUF + ((it & 1) ? 0 : SM_B_BUF);
      *(uint4*)(e + BOFF(br,bc))    = rb0;
      *(uint4*)(e + BOFF(br+16,bc)) = rb1;
    }
  }

  #pragma unroll
  for (int i = 0; i < 4; i++) {
    const int r0 = m0 + wm*64 + i*16 + (lane >> 2);
    #pragma unroll
    for (int j = 0; j < 4; j++) {
      const int cN = n0 + wn*32 + j*8 + (lane & 3)*2;
      const float2 bv = *(const float2*)(bias + cN);
      *(float2*)(C + (size_t)r0*DMODEL + cN) =
          make_float2(acc[i][j].x + bv.x, acc[i][j].y + bv.y);
      *(float2*)(C + (size_t)(r0+8)*DMODEL + cN) =
          make_float2(acc[i][j].z + bv.x, acc[i][j].w + bv.y);
    }
  }
}

// ---------------------------------------------------------------------------
// MMA flash attention (causal, unscaled). bf16x3 for both QK^T and PV.
// CTA: 64 q-rows, 4 warps (16 rows each), BC=64 key tiles, dk=64.
// SMEM tiles row-major, 128B rows, 16B-chunk XOR swizzle.
//   Q (A-frag, ldsm), K (B-frag via ldsm NON-trans on [j][d]),
//   V (B-frag via ldsm trans on [j][d], same as GEMM's W).
// P converted C-frag -> A-frag purely in registers.
// ---------------------------------------------------------------------------
#define FBR 64
#define FBC 64
#define TOFF(r,c) ((r)*128 + ((((c) ^ ((r)&7))) * 16))
#define QHI_OFF 0
#define QLO_OFF 8192
#define KHI_OFF 16384
#define KLO_OFF 24576
#define VHI_OFF 32768
#define VLO_OFF 40960

__device__ __forceinline__ void stage_split(
    const float* __restrict__ g, unsigned char* hib, unsigned char* lob, int t) {
  #pragma unroll
  for (int p = 0; p < 8; p++) {
    const int r = p*8 + (t >> 4), d = (t & 15)*4;
    float4 v = *(const float4*)(g + (size_t)r*DMODEL + d);
    __nv_bfloat16 h0 = __float2bfloat16_rn(v.x), h1 = __float2bfloat16_rn(v.y),
                  h2 = __float2bfloat16_rn(v.z), h3 = __float2bfloat16_rn(v.w);
    __nv_bfloat16 l0 = __float2bfloat16_rn(v.x - __bfloat162float(h0)),
                  l1 = __float2bfloat16_rn(v.y - __bfloat162float(h1)),
                  l2 = __float2bfloat16_rn(v.z - __bfloat162float(h2)),
                  l3 = __float2bfloat16_rn(v.w - __bfloat162float(h3));
    const uint off = TOFF(r, d >> 3) + (d & 7)*2;
    uint2 hv; hv.x = packbf(h0, h1); hv.y = packbf(h2, h3);
    uint2 lv; lv.x = packbf(l0, l1); lv.y = packbf(l2, l3);
    *(uint2*)(hib + off) = hv;
    *(uint2*)(lob + off) = lv;
  }
}

__global__ __launch_bounds__(128) void flash_mma(
    const float* __restrict__ Q, const float* __restrict__ K,
    const float* __restrict__ V, float* __restrict__ O) {
  __shared__ __align__(16) unsigned char sm[49152];
  const int b = blockIdx.z, h = blockIdx.y;
  const int q0 = (gridDim.x - 1 - blockIdx.x) * FBR;  // heavy blocks first
  const int t = threadIdx.x, lane = t & 31, wm = t >> 5;
  const uint sb = (uint)__cvta_generic_to_shared(sm);

  const float* Qg = Q + ((size_t)(b*SEQ + q0))*DMODEL + h*DHEAD;
  const float* Kg = K + ((size_t)(b*SEQ))*DMODEL + h*DHEAD;
  const float* Vg = V + ((size_t)(b*SEQ))*DMODEL + h*DHEAD;

  // stage Q once, then keep its A-frags resident
  stage_split(Qg, sm + QHI_OFF, sm + QLO_OFF, t);
  __syncthreads();
  uint4 qhi[4], qlo[4];
  #pragma unroll
  for (int ks = 0; ks < 4; ks++) {
    const uint off = TOFF(wm*16 + (lane & 15), ks*2 + (lane >> 4));
    ldsm_x4(qhi[ks], sb + QHI_OFF + off);
    ldsm_x4(qlo[ks], sb + QLO_OFF + off);
  }

  float4 o[8];
  #pragma unroll
  for (int i = 0; i < 8; i++) o[i] = make_float4(0.f,0.f,0.f,0.f);
  float m0 = -INFINITY, m1 = -INFINITY, l0 = 0.f, l1 = 0.f;

  const int kend = q0 >> 6;   // diagonal tile index
  for (int kt = 0; kt <= kend; kt++) {
    const int j0 = kt * FBC;
    __syncthreads();
    stage_split(Kg + (size_t)j0*DMODEL, sm + KHI_OFF, sm + KLO_OFF, t);
    stage_split(Vg + (size_t)j0*DMODEL, sm + VHI_OFF, sm + VLO_OFF, t);
    __syncthreads();

    // ---- S = Q.K^T (bf16x3) ----
    float4 sacc[8];
    #pragma unroll
    for (int i = 0; i < 8; i++) sacc[i] = make_float4(0.f,0.f,0.f,0.f);
    #pragma unroll
    for (int pass = 0; pass < 3; pass++) {
      const uint4* aq = (pass == 2) ? qlo : qhi;
      const uint kb = sb + ((pass == 1) ? KLO_OFF : KHI_OFF);
      #pragma unroll
      for (int ks = 0; ks < 4; ks++) {
        #pragma unroll
        for (int jt = 0; jt < 4; jt++) {
          uint4 fb;
          ldsm_x4(fb, kb + TOFF(jt*16 + (lane & 15), ks*2 + (lane >> 4)));
          mma_bf16(sacc[2*jt],   aq[ks], fb.x, fb.z);
          mma_bf16(sacc[2*jt+1], aq[ks], fb.y, fb.w);
        }
      }
    }

    // ---- causal mask (diagonal tile only) ----
    if (kt == kend) {
      const int r0l = wm*16 + (lane >> 2), r1l = r0l + 8;
      #pragma unroll
      for (int nt = 0; nt < 8; nt++) {
        const int c = nt*8 + (lane & 3)*2;
        if (c     > r0l) sacc[nt].x = -INFINITY;
        if (c + 1 > r0l) sacc[nt].y = -INFINITY;
        if (c     > r1l) sacc[nt].z = -INFINITY;
        if (c + 1 > r1l) sacc[nt].w = -INFINITY;
      }
    }

    // ---- online softmax ----
    float mx0 = -INFINITY, mx1 = -INFINITY;
    #pragma unroll
    for (int nt = 0; nt < 8; nt++) {
      mx0 = fmaxf(mx0, fmaxf(sacc[nt].x, sacc[nt].y));
      mx1 = fmaxf(mx1, fmaxf(sacc[nt].z, sacc[nt].w));
    }
    mx0 = fmaxf(mx0, __shfl_xor_sync(0xffffffffu, mx0, 1));
    mx0 = fmaxf(mx0, __shfl_xor_sync(0xffffffffu, mx0, 2));
    mx1 = fmaxf(mx1, __shfl_xor_sync(0xffffffffu, mx1, 1));
    mx1 = fmaxf(mx1, __shfl_xor_sync(0xffffffffu, mx1, 2));
    const float mn0 = fmaxf(m0, mx0), mn1 = fmaxf(m1, mx1);
    const float es0 = __expf(m0 - mn0), es1 = __expf(m1 - mn1);
    m0 = mn0; m1 = mn1;
    l0 *= es0; l1 *= es1;
    #pragma unroll
    for (int i = 0; i < 8; i++) {
      o[i].x *= es0; o[i].y *= es0; o[i].z *= es1; o[i].w *= es1;
    }

    // ---- P = exp(S - m): C-frag -> A-frag in registers, bf16 hi/lo ----
    uint4 pahi[4], palo[4];
    #pragma unroll
    for (int pr = 0; pr < 4; pr++) {
      float4 pa, pb;
      pa.x = __expf(sacc[2*pr].x   - mn0); pa.y = __expf(sacc[2*pr].y   - mn0);
      pa.z = __expf(sacc[2*pr].z   - mn1); pa.w = __expf(sacc[2*pr].w   - mn1);
      pb.x = __expf(sacc[2*pr+1].x - mn0); pb.y = __expf(sacc[2*pr+1].y - mn0);
      pb.z = __expf(sacc[2*pr+1].z - mn1); pb.w = __expf(sacc[2*pr+1].w - mn1);
      l0 += pa.x + pa.y + pb.x + pb.y;
      l1 += pa.z + pa.w + pb.z + pb.w;
      __nv_bfloat16 hx, hy, hz, hw;
      // tile 2pr -> a0 (rows r, k0-7), a1 (rows r+8, k0-7)
      hx = __float2bfloat16_rn(pa.x); hy = __float2bfloat16_rn(pa.y);
      hz = __float2bfloat16_rn(pa.z); hw = __float2bfloat16_rn(pa.w);
      pahi[pr].x = packbf(hx, hy); pahi[pr].y = packbf(hz, hw);
      palo[pr].x = packbf(__float2bfloat16_rn(pa.x - __bfloat162float(hx)),
                          __float2bfloat16_rn(pa.y - __bfloat162float(hy)));
      palo[pr].y = packbf(__float2bfloat16_rn(pa.z - __bfloat162float(hz)),
                          __float2bfloat16_rn(pa.w - __bfloat162float(hw)));
      // tile 2pr+1 -> a2 (rows r, k8-15), a3 (rows r+8, k8-15)
      hx = __float2bfloat16_rn(pb.x); hy = __float2bfloat16_rn(pb.y);
      hz = __float2bfloat16_rn(pb.z); hw = __float2bfloat16_rn(pb.w);
      pahi[pr].z = packbf(hx, hy); pahi[pr].w = packbf(hz, hw);
      palo[pr].z = packbf(__float2bfloat16_rn(pb.x - __bfloat162float(hx)),
                          __float2bfloat16_rn(pb.y - __bfloat162float(hy)));
      palo[pr].w = packbf(__float2bfloat16_rn(pb.z - __bfloat162float(hz)),
                          __float2bfloat16_rn(pb.w - __bfloat162float(hw)));
    }

    // ---- O += P.V (bf16x3) ----
    #pragma unroll
    for (int pass = 0; pass < 3; pass++) {
      const uint4* ap = (pass == 2) ? palo : pahi;
      const uint vb = sb + ((pass == 1) ? VLO_OFF : VHI_OFF);
      #pragma unroll
      for (int ks = 0; ks < 4; ks++) {
        #pragma unroll
        for (int dt = 0; dt < 4; dt++) {
          uint4 fb;
          ldsm_x4t(fb, vb + TOFF(ks*16 + (lane & 15), dt*2 + (lane >> 4)));
          mma_bf16(o[2*dt],   ap[ks], fb.x, fb.y);
          mma_bf16(o[2*dt+1], ap[ks], fb.z, fb.w);
        }
      }
    }
  }

  // ---- finalize: divide by rowsum, store fp32 ----
  l0 += __shfl_xor_sync(0xffffffffu, l0, 1);
  l0 += __shfl_xor_sync(0xffffffffu, l0, 2);
  l1 += __shfl_xor_sync(0xffffffffu, l1, 1);
  l1 += __shfl_xor_sync(0xffffffffu, l1, 2);
  const float inv0 = 1.0f / l0, inv1 = 1.0f / l1;
  const int gr0 = b*SEQ + q0 + wm*16 + (lane >> 2);
  #pragma unroll
  for (int dt = 0; dt < 8; dt++) {
    const int col = h*DHEAD + dt*8 + (lane & 3)*2;
    *(float2*)(O + (size_t)gr0*DMODEL + col) =
        make_float2(o[dt].x * inv0, o[dt].y * inv0);
    *(float2*)(O + (size_t)(gr0 + 8)*DMODEL + col) =
        make_float2(o[dt].z * inv1, o[dt].w * inv1);
  }
}

// ---------------------------------------------------------------------------
// Launch
// ---------------------------------------------------------------------------
extern "C" void kernel_launch(void* const* d_in, const int* in_sizes, int n_in,
                              void* d_out, int out_size) {
  const float* query = (const float*)d_in[0];
  const float* key_  = (const float*)d_in[1];
  const float* value = (const float*)d_in[2];
  // d_in[3] = mask (causal tril) -- handled analytically
  const float* W_q = (const float*)d_in[4];
  const float* b_q = (const float*)d_in[5];
  const float* W_k = (const float*)d_in[6];
  const float* b_k = (const float*)d_in[7];
  const float* W_v = (const float*)d_in[8];
  const float* b_v = (const float*)d_in[9];
  const float* W_o = (const float*)d_in[10];
  const float* b_o = (const float*)d_in[11];
  float* out = (float*)d_out;

  float *Qb, *Kb, *Vb, *Ob;
  __nv_bfloat16 *Asp, *Wsp;
  cudaGetSymbolAddress((void**)&Qb, g_Q);
  cudaGetSymbolAddress((void**)&Kb, g_K);
  cudaGetSymbolAddress((void**)&Vb, g_V);
  cudaGetSymbolAddress((void**)&Ob, g_O);
  cudaGetSymbolAddress((void**)&Asp, g_Asp);
  cudaGetSymbolAddress((void**)&Wsp, g_Wsp);

  const int act_blocks = (MTOT*DMODEL/4 + 255)/256;
  const int w_blocks   = (DMODEL*DMODEL/4 + 255)/256;
  dim3 gg(DMODEL/128, MTOT/128);

  split_act<<<act_blocks, 256>>>(query, Asp, MTOT);
  split_w<<<w_blocks, 256>>>(W_q, Wsp);
  gemm_bf16x3<<<gg, 256>>>(Asp, Wsp, b_q, Qb);

  split_act<<<act_blocks, 256>>>(key_, Asp, MTOT);
  split_w<<<w_blocks, 256>>>(W_k, Wsp);
  gemm_bf16x3<<<gg, 256>>>(Asp, Wsp, b_k, Kb);

  split_act<<<act_blocks, 256>>>(value, Asp, MTOT);
  split_w<<<w_blocks, 256>>>(W_v, Wsp);
  gemm_bf16x3<<<gg, 256>>>(Asp, Wsp, b_v, Vb);

  flash_mma<<<dim3(SEQ/FBR, NHEAD, BATCH), 128>>>(Qb, Kb, Vb, Ob);

  split_act<<<act_blocks, 256>>>(Ob, Asp, MTOT);
  split_w<<<w_blocks, 256>>>(W_o, Wsp);
  gemm_bf16x3<<<gg, 256>>>(Asp, Wsp, b_o, out);
}